// round 3
// baseline (speedup 1.0000x reference)
#include <cuda_runtime.h>

// 2-layer GRU (B=2048, T=1024, D=64, H=32) + sigmoid head.
// Kernel 1: precompute gx[t][b][96] = w_ih0 @ x[b][t] + b_ih0  (fma-bound, R=8)
// Kernel 2: fused recurrence, 128 CTAs x 4 warps, R=4 batch/warp, lane=hidden idx,
//           weights in smem (k-quad-major), packed fp32 FMA (fma.rn.f32x2),
//           double-buffered h smem -> 1 syncwarp/step, gx prefetched 1 step ahead.

#define TT 1024
#define NB 2048
#define DHID 32

typedef unsigned long long u64;

// 805 MB scratch for the precomputed input-gate contributions, layout [t][b][96]
__device__ float g_gx[(size_t)TT * NB * 96];

__device__ __forceinline__ u64 pk(float lo, float hi) {
    u64 r; asm("mov.b64 %0, {%1,%2};" : "=l"(r) : "f"(lo), "f"(hi)); return r;
}
__device__ __forceinline__ float hsum(u64 v) {
    float lo, hi; asm("mov.b64 {%0,%1}, %2;" : "=f"(lo), "=f"(hi) : "l"(v));
    return lo + hi;
}
__device__ __forceinline__ u64 fma2(u64 a, u64 b, u64 c) {
    u64 d; asm("fma.rn.f32x2 %0, %1, %2, %3;" : "=l"(d) : "l"(a), "l"(b), "l"(c));
    return d;
}
__device__ __forceinline__ float sig_(float v) {
    return __fdividef(1.0f, 1.0f + __expf(-v));
}
__device__ __forceinline__ float tanh_(float v) {
    v = fminf(fmaxf(v, -30.0f), 30.0f);
    float e = __expf(-2.0f * v);
    return (1.0f - e) * __fdividef(1.0f, 1.0f + e);
}

// accumulate 3 gate rows (lane, 32+lane, 64+lane) over KQ k-quads for R batch
// elems. w: [KQ][96] float4 smem. xb: per-warp smem activations, stride XS.
template<int KQ, int XS, int R>
__device__ __forceinline__ void gacc(const float4* __restrict__ w,
                                     const float* __restrict__ xb, int lane,
                                     u64* __restrict__ ar, u64* __restrict__ az,
                                     u64* __restrict__ an)
{
#pragma unroll
    for (int kq = 0; kq < KQ; kq++) {
        float4 wr = w[kq * 96 + lane];
        float4 wz = w[kq * 96 + 32 + lane];
        float4 wn = w[kq * 96 + 64 + lane];
        u64 wrl = pk(wr.x, wr.y), wrh = pk(wr.z, wr.w);
        u64 wzl = pk(wz.x, wz.y), wzh = pk(wz.z, wz.w);
        u64 wnl = pk(wn.x, wn.y), wnh = pk(wn.z, wn.w);
#pragma unroll
        for (int b = 0; b < R; b++) {
            float4 xq = *(const float4*)(xb + b * XS + kq * 4);  // broadcast
            u64 xl = pk(xq.x, xq.y), xh = pk(xq.z, xq.w);
            ar[b] = fma2(wrl, xl, ar[b]);
            az[b] = fma2(wzl, xl, az[b]);
            an[b] = fma2(wnl, xl, an[b]);
            ar[b] = fma2(wrh, xh, ar[b]);
            az[b] = fma2(wzh, xh, az[b]);
            an[b] = fma2(wnh, xh, an[b]);
        }
    }
}

// ---------------------------------------------------------------------------
// Kernel 1: gx[t][b][g] = sum_k w_ih0[g][k] * x[b][t][k] + b_ih0[g]
// grid 512 x 128 thr. Warp handles 8 batch elems x 128 timesteps.
// smem: wi0 packed [16][96] float4 (24.6KB) + per-warp x staging (8b*64*2 slots)
// ---------------------------------------------------------------------------
#define PC_XB_OFF 6144
#define PC_SMEM_FLOATS (6144 + 4 * 1024)
#define PC_SMEM_BYTES (PC_SMEM_FLOATS * 4)

__global__ void __launch_bounds__(128, 4) gx_precompute(
    const float* __restrict__ x,
    const float* __restrict__ w_ih0,
    const float* __restrict__ b_ih0)
{
    extern __shared__ float sm[];
    const int tid = threadIdx.x, lane = tid & 31, warp = tid >> 5;

    // pack w_ih0 [96][64] -> [16 kq][96] float4
    {
        const float4* s = (const float4*)w_ih0;
        float4* d = (float4*)sm;
        for (int i = tid; i < 96 * 16; i += 128) {
            int g = i % 96, kq = i / 96;
            d[kq * 96 + g] = s[g * 16 + kq];
        }
    }
    __syncthreads();

    const int grp = blockIdx.x >> 1;                  // 0..255, 8 batch each
    const int b0 = grp * 8;
    const int chunk = (blockIdx.x & 1) * 4 + warp;    // 0..7, 128 t each
    const int t0 = chunk * 128;

    const float4* wi0 = (const float4*)sm;
    float* xbw = sm + PC_XB_OFF + warp * 1024;        // 2 slots x 512 floats
    float4* xbw4 = (float4*)xbw;

    const u64 sR = pk(b_ih0[lane], 0.0f);
    const u64 sZ = pk(b_ih0[32 + lane], 0.0f);
    const u64 sN = pk(b_ih0[64 + lane], 0.0f);

    // lane covers 4 (b,q) slots of the 8b x 16q = 128-quad x tile
    const int q = lane & 15;
    const int bl = lane >> 4;                          // 0 or 1
    const float4* xp[4];
    float4 xr[4];
#pragma unroll
    for (int s = 0; s < 4; s++) {
        int b = bl + 2 * s;
        xp[s] = (const float4*)x + ((size_t)(b0 + b) * TT + t0) * 16 + q;
        xr[s] = *xp[s];
    }

    int p = 0;
    for (int t = t0; t < t0 + 128; t++) {
        // stage x(t)
#pragma unroll
        for (int s = 0; s < 4; s++)
            xbw4[p * 128 + (bl + 2 * s) * 16 + q] = xr[s];
        __syncwarp();
        if (t < t0 + 127) {
#pragma unroll
            for (int s = 0; s < 4; s++) { xp[s] += 16; xr[s] = *xp[s]; }
        }

        u64 ar[8], az[8], an[8];
#pragma unroll
        for (int b = 0; b < 8; b++) { ar[b] = sR; az[b] = sZ; an[b] = sN; }
        gacc<16, 64, 8>(wi0, xbw + p * 512, lane, ar, az, an);

        float* o = g_gx + ((size_t)t * NB + b0) * 96 + lane;
#pragma unroll
        for (int b = 0; b < 8; b++) {
            o[b * 96]      = hsum(ar[b]);
            o[b * 96 + 32] = hsum(az[b]);
            o[b * 96 + 64] = hsum(an[b]);
        }
        p ^= 1;
    }
}

// ---------------------------------------------------------------------------
// Kernel 2: recurrence. 128 CTAs x 128 thr; warp owns 4 batch elems.
// ---------------------------------------------------------------------------
#define WH0_OFF 0        // [8][96] float4
#define WI1_OFF 3072
#define WH1_OFF 6144
#define H0B_OFF 9216     // 4 warps * 2 slots * 128
#define H1B_OFF 10240
#define RC_SMEM_FLOATS 11264
#define RC_SMEM_BYTES (RC_SMEM_FLOATS * 4)

__global__ void __launch_bounds__(128, 1) gru2_recur(
    const float* __restrict__ w_hh0, const float* __restrict__ b_hh0,
    const float* __restrict__ w_ih1, const float* __restrict__ w_hh1,
    const float* __restrict__ b_ih1, const float* __restrict__ b_hh1,
    const float* __restrict__ w_cls, const float* __restrict__ b_cls,
    float* __restrict__ out)
{
    extern __shared__ float sm[];
    const int tid = threadIdx.x, lane = tid & 31, warp = tid >> 5;

    // pack the three [96][32] matrices -> [8 kq][96] float4
    {
        const float4* s0 = (const float4*)w_hh0; float4* d0 = (float4*)(sm + WH0_OFF);
        const float4* s1 = (const float4*)w_ih1; float4* d1 = (float4*)(sm + WI1_OFF);
        const float4* s2 = (const float4*)w_hh1; float4* d2 = (float4*)(sm + WH1_OFF);
        for (int i = tid; i < 96 * 8; i += 128) {
            int g = i % 96, kq = i / 96;
            d0[kq * 96 + g] = s0[g * 8 + kq];
            d1[kq * 96 + g] = s1[g * 8 + kq];
            d2[kq * 96 + g] = s2[g * 8 + kq];
        }
        for (int i = tid; i < 2048; i += 128) sm[H0B_OFF + i] = 0.0f;
    }
    __syncthreads();

    const int wg = blockIdx.x * 4 + warp;   // 0..511
    const int b0 = wg * 4;

    float* h0b = sm + H0B_OFF + warp * 256;   // 2 slots x 128
    float* h1b = sm + H1B_OFF + warp * 256;
    const float4* wh0 = (const float4*)(sm + WH0_OFF);
    const float4* wi1 = (const float4*)(sm + WI1_OFF);
    const float4* wh1 = (const float4*)(sm + WH1_OFF);

    const float bhh0_r = b_hh0[lane];
    const float bhh0_z = b_hh0[32 + lane];
    const u64 iA_hn = pk(b_hh0[64 + lane], 0.0f);
    const u64 iB_r  = pk(b_ih1[lane]      + b_hh1[lane],      0.0f);
    const u64 iB_z  = pk(b_ih1[32 + lane] + b_hh1[32 + lane], 0.0f);
    const u64 iB_xn = pk(b_ih1[64 + lane], 0.0f);
    const u64 iB_hn = pk(b_hh1[64 + lane], 0.0f);
    const float wclsl = w_cls[lane];
    const float bcls = b_cls[0];

    float hA[4] = {0.f, 0.f, 0.f, 0.f};
    float hB[4] = {0.f, 0.f, 0.f, 0.f};

    // gx loads: coalesced scalar LDG, prefetched one step ahead
    const float* gx = g_gx;
    float cr[4], cz[4], cn[4], nr[4], nz[4], nn[4];
#pragma unroll
    for (int b = 0; b < 4; b++) {
        const float* p = gx + (size_t)(b0 + b) * 96 + lane;
        cr[b] = p[0]; cz[b] = p[32]; cn[b] = p[64];
    }

    for (int t = 0; t < TT; t++) {
        if (t < TT - 1) {
#pragma unroll
            for (int b = 0; b < 4; b++) {
                const float* p = gx + ((size_t)(t + 1) * NB + b0 + b) * 96 + lane;
                nr[b] = p[0]; nz[b] = p[32]; nn[b] = p[64];
            }
        }
        const int pcur = t & 1;
        float* h0w = h0b + pcur * 128;
        float* h0r = h0b + (pcur ^ 1) * 128;
        float* h1w = h1b + pcur * 128;
        float* h1r = h1b + (pcur ^ 1) * 128;

        // ---------- layer 0 ----------
        u64 ar[4], az[4], axn[4], ahn[4];
#pragma unroll
        for (int b = 0; b < 4; b++) {
            ar[b] = pk(cr[b], bhh0_r);
            az[b] = pk(cz[b], bhh0_z);
            axn[b] = pk(cn[b], 0.0f);
            ahn[b] = iA_hn;
        }
        gacc<8, 32, 4>(wh0, h0r, lane, ar, az, ahn);
#pragma unroll
        for (int b = 0; b < 4; b++) {
            float r = sig_(hsum(ar[b]));
            float z = sig_(hsum(az[b]));
            float n = tanh_(hsum(axn[b]) + r * hsum(ahn[b]));
            hA[b] = (1.0f - z) * n + z * hA[b];
            h0w[b * 32 + lane] = hA[b];
        }
        __syncwarp();

        // ---------- layer 1 ----------
#pragma unroll
        for (int b = 0; b < 4; b++) { ar[b] = iB_r; az[b] = iB_z; axn[b] = iB_xn; ahn[b] = iB_hn; }
        gacc<8, 32, 4>(wi1, h0w, lane, ar, az, axn);
        gacc<8, 32, 4>(wh1, h1r, lane, ar, az, ahn);
#pragma unroll
        for (int b = 0; b < 4; b++) {
            float r = sig_(hsum(ar[b]));
            float z = sig_(hsum(az[b]));
            float n = tanh_(hsum(axn[b]) + r * hsum(ahn[b]));
            hB[b] = (1.0f - z) * n + z * hB[b];
            h1w[b * 32 + lane] = hB[b];
        }
#pragma unroll
        for (int b = 0; b < 4; b++) { cr[b] = nr[b]; cz[b] = nz[b]; cn[b] = nn[b]; }
    }

    // ---------- outputs: [y (2048)] [hidden (2,2048,32)] ----------
#pragma unroll
    for (int b = 0; b < 4; b++) {
        int gb = b0 + b;
        out[2048 + gb * DHID + lane]         = hA[b];
        out[2048 + 65536 + gb * DHID + lane] = hB[b];
        float p = wclsl * hB[b];
#pragma unroll
        for (int o = 16; o > 0; o >>= 1) p += __shfl_xor_sync(0xFFFFFFFFu, p, o);
        if (lane == 0) out[gb] = sig_(p + bcls);
    }
}

extern "C" void kernel_launch(void* const* d_in, const int* in_sizes, int n_in,
                              void* d_out, int out_size)
{
    const float* x     = (const float*)d_in[0];
    const float* w_ih0 = (const float*)d_in[1];
    const float* w_hh0 = (const float*)d_in[2];
    const float* b_ih0 = (const float*)d_in[3];
    const float* b_hh0 = (const float*)d_in[4];
    const float* w_ih1 = (const float*)d_in[5];
    const float* w_hh1 = (const float*)d_in[6];
    const float* b_ih1 = (const float*)d_in[7];
    const float* b_hh1 = (const float*)d_in[8];
    const float* w_cls = (const float*)d_in[9];
    const float* b_cls = (const float*)d_in[10];
    float* out = (float*)d_out;

    cudaFuncSetAttribute(gx_precompute, cudaFuncAttributeMaxDynamicSharedMemorySize,
                         PC_SMEM_BYTES);
    cudaFuncSetAttribute(gru2_recur, cudaFuncAttributeMaxDynamicSharedMemorySize,
                         RC_SMEM_BYTES);

    gx_precompute<<<512, 128, PC_SMEM_BYTES>>>(x, w_ih0, b_ih0);
    gru2_recur<<<128, 128, RC_SMEM_BYTES>>>(w_hh0, b_hh0, w_ih1, w_hh1,
                                            b_ih1, b_hh1, w_cls, b_cls, out);
}